// round 1
// baseline (speedup 1.0000x reference)
#include <cuda_runtime.h>
#include <math.h>

#define NS 25
#define NQ 50
#define NV 75
#define SEQ 12
#define DIM 1152
#define HH 2
#define DH 576
#define NTUP 220
#define WAY 5
#define SHOT 5
#define KROWS (NQ*NTUP)      /* 11000 query-tuple rows */
#define SROWS (NS*NTUP)      /* 5500 support-tuple rows */
#define SKCOL (SHOT*NTUP)    /* 1100 = softmax row length */

// ---------------- device scratch (static, no malloc) ----------------
__device__ float g_pe[SEQ*DIM];
__device__ int   g_tuples[NTUP*3];
__device__ float g_P[NV*SEQ*3*2304];           // per-frame partial projections [900][6912]
__device__ float g_qk[HH][KROWS*DH];           // LN'd K-proj of queries, head-split
__device__ float g_sk[HH][SROWS*DH];           // LN'd K-proj of support, head-split
__device__ float g_sv[HH][SROWS*DH];           // V-proj of support, head-split
__device__ float g_qv[NQ*NTUP*DIM];            // V-proj of queries, full width
__device__ float g_scores[NQ*WAY*HH*NTUP*SKCOL];  // 484 MB, reused in-place for attn
__device__ float g_proto[NQ*WAY*NTUP*DIM];     // 507 MB

// ---------------- init: PE table + tuple index table ----------------
__global__ void k_init() {
    int tid = threadIdx.x;
    for (int i = tid; i < SEQ*576; i += blockDim.x) {
        int p = i / 576, j = i % 576;
        double dv = exp(-(double)(2*j) * (log(10000.0) / 1152.0));
        double ang = (double)p * dv;
        g_pe[p*DIM + 2*j]     = (float)(sin(ang) * 0.1);
        g_pe[p*DIM + 2*j + 1] = (float)(cos(ang) * 0.1);
    }
    if (tid == 0) {
        int idx = 0;
        for (int a = 0; a < SEQ; a++)
            for (int b = a+1; b < SEQ; b++)
                for (int c = b+1; c < SEQ; c++) {
                    g_tuples[idx*3+0] = a;
                    g_tuples[idx*3+1] = b;
                    g_tuples[idx*3+2] = c;
                    idx++;
                }
    }
}

// ---------------- K1: projection GEMM ----------------
// C[m=900][n=6912]: m=(v,f), n=(j, o) with o in [0,2304): o<1152 -> k_w, else v_w.
// A[m][k] = x[v][f][k] + pe[f][k], B[k][n] = W[(j*1152+k)*1152 + o%1152]
__global__ __launch_bounds__(256) void k_proj(
    const float* __restrict__ sup, const float* __restrict__ qry,
    const float* __restrict__ kw,  const float* __restrict__ vw)
{
    __shared__ float As[16][128];
    __shared__ float Bs[16][128];
    __shared__ const float* rowptr[128];
    __shared__ int rowpe[128];

    const int m0 = blockIdx.y * 128, n0 = blockIdx.x * 128;
    const int tid = threadIdx.x, tx = tid % 16, ty = tid / 16;

    const int j = n0 / 2304;
    const int o0 = n0 % 2304;
    const float* wmat = (o0 < 1152) ? kw : vw;
    const int ocol0 = o0 % 1152;

    if (tid < 128) {
        int m = m0 + tid;
        if (m < NV*SEQ) {
            int v = m / SEQ, f = m % SEQ;
            rowptr[tid] = (v < NS) ? (sup + (v*SEQ + f)*DIM)
                                   : (qry + ((v - NS)*SEQ + f)*DIM);
            rowpe[tid] = f * DIM;
        } else {
            rowptr[tid] = nullptr; rowpe[tid] = 0;
        }
    }
    __syncthreads();

    float c[8][8] = {};
    for (int k0 = 0; k0 < 1152; k0 += 16) {
        #pragma unroll
        for (int i = tid; i < 2048; i += 256) {
            int r = i >> 4, kk = i & 15;
            const float* sp = rowptr[r];
            As[kk][r] = sp ? (sp[k0 + kk] + g_pe[rowpe[r] + k0 + kk]) : 0.f;
        }
        #pragma unroll
        for (int i = tid; i < 2048; i += 256) {
            int kk = i >> 7, col = i & 127;
            Bs[kk][col] = wmat[(j*1152 + k0 + kk)*1152 + ocol0 + col];
        }
        __syncthreads();
        #pragma unroll
        for (int kk = 0; kk < 16; kk++) {
            float4 a0 = *(const float4*)&As[kk][ty*8];
            float4 a1 = *(const float4*)&As[kk][ty*8 + 4];
            float4 b0 = *(const float4*)&Bs[kk][tx*8];
            float4 b1 = *(const float4*)&Bs[kk][tx*8 + 4];
            float a[8] = {a0.x,a0.y,a0.z,a0.w,a1.x,a1.y,a1.z,a1.w};
            float b[8] = {b0.x,b0.y,b0.z,b0.w,b1.x,b1.y,b1.z,b1.w};
            #pragma unroll
            for (int ii = 0; ii < 8; ii++)
                #pragma unroll
                for (int jj = 0; jj < 8; jj++)
                    c[ii][jj] += a[ii] * b[jj];
        }
        __syncthreads();
    }
    #pragma unroll
    for (int ii = 0; ii < 8; ii++) {
        int m = m0 + ty*8 + ii;
        if (m < NV*SEQ) {
            float* dst = g_P + m*6912 + n0 + tx*8;
            #pragma unroll
            for (int jj = 0; jj < 8; jj++) dst[jj] = c[ii][jj];
        }
    }
}

// ---------------- K2: tuple combine + bias + LayerNorm, scatter ----------------
__global__ __launch_bounds__(128) void k_combine(
    const float* __restrict__ kb, const float* __restrict__ vb,
    const float* __restrict__ lg, const float* __restrict__ lb)
{
    const int bid = blockIdx.x;         // v*220 + t
    const int v = bid / NTUP, t = bid % NTUP;
    const int tid = threadIdx.x;
    __shared__ float red[128];
    __shared__ int fr[3];
    if (tid < 3) fr[tid] = g_tuples[t*3 + tid];
    __syncthreads();

    float kv[9];
    float lsum = 0.f, lsq = 0.f;
    const float* Pbase = g_P + v*SEQ*3*2304;
    #pragma unroll
    for (int ii = 0; ii < 9; ii++) {
        int d = tid + ii*128;
        float ka = kb[d];
        float va = vb[d];
        #pragma unroll
        for (int j = 0; j < 3; j++) {
            const float* p = Pbase + (fr[j]*3 + j)*2304;
            ka += p[d];
            va += p[1152 + d];
        }
        kv[ii] = ka;
        lsum += ka; lsq += ka*ka;
        if (v < NS) {
            int h = d / DH, dd = d % DH;
            g_sv[h][(v*NTUP + t)*DH + dd] = va;
        } else {
            g_qv[((v - NS)*NTUP + t)*DIM + d] = va;
        }
    }
    red[tid] = lsum; __syncthreads();
    for (int s = 64; s > 0; s >>= 1) { if (tid < s) red[tid] += red[tid+s]; __syncthreads(); }
    float mu = red[0] * (1.f/1152.f);
    __syncthreads();
    red[tid] = lsq; __syncthreads();
    for (int s = 64; s > 0; s >>= 1) { if (tid < s) red[tid] += red[tid+s]; __syncthreads(); }
    float var = red[0] * (1.f/1152.f) - mu*mu;
    float rstd = rsqrtf(var + 1e-5f);

    #pragma unroll
    for (int ii = 0; ii < 9; ii++) {
        int d = tid + ii*128;
        float o = (kv[ii] - mu) * rstd * lg[d] + lb[d];
        int h = d / DH, dd = d % DH;
        if (v < NS) g_sk[h][(v*NTUP + t)*DH + dd] = o;
        else        g_qk[h][((v - NS)*NTUP + t)*DH + dd] = o;
    }
}

// ---------------- K3: scores GEMM (NT): C[m=11000][n=1100] per (w,h) ----------------
__global__ __launch_bounds__(256) void k_scores() {
    const int z = blockIdx.z, w = z >> 1, h = z & 1;
    const int n0 = blockIdx.x * 128, m0 = blockIdx.y * 128;
    __shared__ float As[16][128], Bs[16][128];
    const int tid = threadIdx.x, tx = tid % 16, ty = tid / 16;
    const float* A = g_qk[h];
    const float* B = g_sk[h] + w * SKCOL * DH;

    float c[8][8] = {};
    for (int k0 = 0; k0 < DH; k0 += 16) {
        #pragma unroll
        for (int i = tid; i < 2048; i += 256) {
            int r = i >> 4, kk = i & 15;
            int m = m0 + r;
            As[kk][r] = (m < KROWS) ? A[m*DH + k0 + kk] : 0.f;
        }
        #pragma unroll
        for (int i = tid; i < 2048; i += 256) {
            int r = i >> 4, kk = i & 15;
            int n = n0 + r;
            Bs[kk][r] = (n < SKCOL) ? B[n*DH + k0 + kk] : 0.f;
        }
        __syncthreads();
        #pragma unroll
        for (int kk = 0; kk < 16; kk++) {
            float4 a0 = *(const float4*)&As[kk][ty*8];
            float4 a1 = *(const float4*)&As[kk][ty*8 + 4];
            float4 b0 = *(const float4*)&Bs[kk][tx*8];
            float4 b1 = *(const float4*)&Bs[kk][tx*8 + 4];
            float a[8] = {a0.x,a0.y,a0.z,a0.w,a1.x,a1.y,a1.z,a1.w};
            float b[8] = {b0.x,b0.y,b0.z,b0.w,b1.x,b1.y,b1.z,b1.w};
            #pragma unroll
            for (int ii = 0; ii < 8; ii++)
                #pragma unroll
                for (int jj = 0; jj < 8; jj++)
                    c[ii][jj] += a[ii] * b[jj];
        }
        __syncthreads();
    }
    const float scale = 1.f / 24.f;   // 1/sqrt(576)
    #pragma unroll
    for (int ii = 0; ii < 8; ii++) {
        int m = m0 + ty*8 + ii;
        if (m < KROWS) {
            int q = m / NTUP, tq = m % NTUP;
            float* dst = g_scores + (size_t)(((q*WAY + w)*HH + h)*NTUP + tq)*SKCOL;
            #pragma unroll
            for (int jj = 0; jj < 8; jj++) {
                int n = n0 + tx*8 + jj;
                if (n < SKCOL) dst[n] = c[ii][jj] * scale;
            }
        }
    }
}

// ---------------- K3b: softmax over rows of 1100 (in place) ----------------
__global__ __launch_bounds__(128) void k_softmax() {
    float* p = g_scores + (size_t)blockIdx.x * SKCOL;
    const int tid = threadIdx.x;
    __shared__ float red[128];
    float ev[9];
    float lmax = -1e30f;
    #pragma unroll
    for (int ii = 0; ii < 9; ii++) {
        int i = tid + ii*128;
        ev[ii] = (i < SKCOL) ? p[i] : -1e30f;
        lmax = fmaxf(lmax, ev[ii]);
    }
    red[tid] = lmax; __syncthreads();
    for (int s = 64; s > 0; s >>= 1) { if (tid < s) red[tid] = fmaxf(red[tid], red[tid+s]); __syncthreads(); }
    float mx = red[0];
    __syncthreads();
    float lsum = 0.f;
    #pragma unroll
    for (int ii = 0; ii < 9; ii++) {
        int i = tid + ii*128;
        if (i < SKCOL) { ev[ii] = expf(ev[ii] - mx); lsum += ev[ii]; }
    }
    red[tid] = lsum; __syncthreads();
    for (int s = 64; s > 0; s >>= 1) { if (tid < s) red[tid] += red[tid+s]; __syncthreads(); }
    float inv = 1.f / red[0];
    #pragma unroll
    for (int ii = 0; ii < 9; ii++) {
        int i = tid + ii*128;
        if (i < SKCOL) p[i] = ev[ii] * inv;
    }
}

// ---------------- K4: proto GEMM (NN): C[m=11000][n=576] per (w,h) ----------------
__global__ __launch_bounds__(256) void k_proto() {
    const int z = blockIdx.z, w = z >> 1, h = z & 1;
    const int n0 = blockIdx.x * 128, m0 = blockIdx.y * 128;
    __shared__ float As[16][128], Bs[16][128];
    __shared__ int rowbase[128];
    const int tid = threadIdx.x, tx = tid % 16, ty = tid / 16;
    const float* B = g_sv[h] + w * SKCOL * DH;

    if (tid < 128) {
        int m = m0 + tid;
        rowbase[tid] = (m < KROWS)
            ? (((m / NTUP * WAY + w)*HH + h)*NTUP + (m % NTUP)) * SKCOL
            : -1;
    }
    __syncthreads();

    float c[8][8] = {};
    for (int k0 = 0; k0 < SKCOL; k0 += 16) {
        #pragma unroll
        for (int i = tid; i < 2048; i += 256) {
            int r = i >> 4, kk = i & 15;
            int k = k0 + kk;
            int rb = rowbase[r];
            As[kk][r] = (rb >= 0 && k < SKCOL) ? g_scores[rb + k] : 0.f;
        }
        #pragma unroll
        for (int i = tid; i < 2048; i += 256) {
            int kk = i >> 7, col = i & 127;
            int k = k0 + kk, n = n0 + col;
            Bs[kk][col] = (k < SKCOL && n < DH) ? B[k*DH + n] : 0.f;
        }
        __syncthreads();
        #pragma unroll
        for (int kk = 0; kk < 16; kk++) {
            float4 a0 = *(const float4*)&As[kk][ty*8];
            float4 a1 = *(const float4*)&As[kk][ty*8 + 4];
            float4 b0 = *(const float4*)&Bs[kk][tx*8];
            float4 b1 = *(const float4*)&Bs[kk][tx*8 + 4];
            float a[8] = {a0.x,a0.y,a0.z,a0.w,a1.x,a1.y,a1.z,a1.w};
            float b[8] = {b0.x,b0.y,b0.z,b0.w,b1.x,b1.y,b1.z,b1.w};
            #pragma unroll
            for (int ii = 0; ii < 8; ii++)
                #pragma unroll
                for (int jj = 0; jj < 8; jj++)
                    c[ii][jj] += a[ii] * b[jj];
        }
        __syncthreads();
    }
    #pragma unroll
    for (int ii = 0; ii < 8; ii++) {
        int m = m0 + ty*8 + ii;
        if (m < KROWS) {
            int q = m / NTUP, tq = m % NTUP;
            float* dst = g_proto + (size_t)((q*WAY + w)*NTUP + tq)*DIM + h*DH;
            #pragma unroll
            for (int jj = 0; jj < 8; jj++) {
                int n = n0 + tx*8 + jj;
                if (n < DH) dst[n] = c[ii][jj];
            }
        }
    }
}

// ---------------- K5: fused diff^2 reduction -> logits ----------------
__global__ __launch_bounds__(256) void k_logits(float* __restrict__ out) {
    const int b = blockIdx.x;           // q*5 + w
    const int q = b / WAY;
    const float* qv = g_qv + (size_t)q * NTUP * DIM;
    const float* pr = g_proto + (size_t)b * NTUP * DIM;
    float acc = 0.f;
    for (int i = threadIdx.x; i < NTUP*DIM; i += 256) {
        float d = qv[i] - pr[i];
        acc += d * d;
    }
    __shared__ float red[256];
    red[threadIdx.x] = acc; __syncthreads();
    for (int s = 128; s > 0; s >>= 1) { if (threadIdx.x < s) red[threadIdx.x] += red[threadIdx.x + s]; __syncthreads(); }
    if (threadIdx.x == 0) out[b] = -red[0] / (float)NTUP;
}

// ---------------- launch ----------------
extern "C" void kernel_launch(void* const* d_in, const int* in_sizes, int n_in,
                              void* d_out, int out_size)
{
    const float* support = (const float*)d_in[0];
    const float* queries = (const float*)d_in[1];
    // d_in[2] = support_labels (int32) — sorted by construction, unused
    const float* k_w  = (const float*)d_in[3];
    const float* k_b  = (const float*)d_in[4];
    const float* v_w  = (const float*)d_in[5];
    const float* v_b  = (const float*)d_in[6];
    const float* ln_g = (const float*)d_in[7];
    const float* ln_b = (const float*)d_in[8];
    float* out = (float*)d_out;

    k_init<<<1, 256>>>();

    dim3 g1(6912/128, (NV*SEQ + 127)/128);           // (54, 8)
    k_proj<<<g1, 256>>>(support, queries, k_w, v_w);

    k_combine<<<NV*NTUP, 128>>>(k_b, v_b, ln_g, ln_b);

    dim3 g3((SKCOL + 127)/128, (KROWS + 127)/128, WAY*HH);  // (9, 86, 10)
    k_scores<<<g3, 256>>>();

    k_softmax<<<NQ*WAY*HH*NTUP, 128>>>();            // 110000 rows

    dim3 g4((DH + 127)/128, (KROWS + 127)/128, WAY*HH);     // (5, 86, 10)
    k_proto<<<g4, 256>>>();

    k_logits<<<NQ*WAY, 256>>>(out);
}

// round 3
// speedup vs baseline: 7.6793x; 7.6793x over previous
#include <cuda_runtime.h>
#include <cuda_bf16.h>
#include <math.h>
#include <stdint.h>

#define NS 25
#define NQ 50
#define NV 75
#define SEQ 12
#define DIM 1152
#define HH 2
#define DH 576
#define NTUP 220
#define WAY 5
#define SHOT 5
#define KROWS (NQ*NTUP)      /* 11000 */
#define MPAD  11008          /* 86*128 */
#define SKCOL (SHOT*NTUP)    /* 1100 */
#define SKP   1152           /* padded */
#define DHP   640            /* padded */
#define KPAD  1152

// ---------------- device scratch (padded to 128 multiples everywhere) ----------------
__device__ float g_pe[SEQ*DIM];
__device__ int   g_tuples[NTUP*3];
__device__ __align__(16) __nv_bfloat16 g_Ap[1024*DIM];               // proj A (x+pe)
__device__ __align__(16) __nv_bfloat16 g_wT[6912*DIM];               // proj B^T
__device__ float g_P[1024*6912];                                     // proj out
__device__ __align__(16) __nv_bfloat16 g_qk[HH][(size_t)MPAD*DH];    // LN K-proj queries
__device__ __align__(16) __nv_bfloat16 g_skz[WAY*HH][(size_t)SKP*DH];// LN K-proj support
__device__ __align__(16) __nv_bfloat16 g_svT[WAY*HH][(size_t)DHP*KPAD]; // V-proj support, transposed
__device__ float g_qv[(size_t)KROWS*DIM];
__device__ float g_scores[WAY*HH][(size_t)MPAD*SKP];
__device__ __align__(16) __nv_bfloat16 g_attn[WAY*HH][(size_t)MPAD*KPAD];
__device__ float g_proto[WAY*HH][(size_t)MPAD*DHP];

// ---------------- helpers ----------------
__device__ __forceinline__ uint32_t smem_u32(const void* p){
    uint32_t a;
    asm("{ .reg .u64 t; cvta.to.shared.u64 t, %1; cvt.u32.u64 %0, t; }" : "=r"(a) : "l"(p));
    return a;
}
#define SW128(x) ((x) ^ (((x)>>3)&0x70))

__device__ __forceinline__ void ldm4(uint32_t* r, uint32_t addr){
    asm volatile("ldmatrix.sync.aligned.m8n8.x4.shared.b16 {%0,%1,%2,%3}, [%4];"
        : "=r"(r[0]), "=r"(r[1]), "=r"(r[2]), "=r"(r[3]) : "r"(addr));
}
__device__ __forceinline__ void mma16816(float* c, const uint32_t* a, uint32_t b0, uint32_t b1){
    asm volatile("mma.sync.aligned.m16n8k16.row.col.f32.bf16.bf16.f32 "
        "{%0,%1,%2,%3}, {%4,%5,%6,%7}, {%8,%9}, {%0,%1,%2,%3};"
        : "+f"(c[0]), "+f"(c[1]), "+f"(c[2]), "+f"(c[3])
        : "r"(a[0]), "r"(a[1]), "r"(a[2]), "r"(a[3]), "r"(b0), "r"(b1));
}
__device__ __forceinline__ void cpa16(uint32_t dst, const void* src){
    asm volatile("cp.async.cg.shared.global [%0], [%1], 16;" :: "r"(dst), "l"(src));
}

// ---------------- init ----------------
__global__ void k_init() {
    int tid = threadIdx.x;
    for (int i = tid; i < SEQ*576; i += blockDim.x) {
        int p = i / 576, j = i % 576;
        double dv = exp(-(double)(2*j) * (log(10000.0) / 1152.0));
        double ang = (double)p * dv;
        g_pe[p*DIM + 2*j]     = (float)(sin(ang) * 0.1);
        g_pe[p*DIM + 2*j + 1] = (float)(cos(ang) * 0.1);
    }
    if (tid == 0) {
        int idx = 0;
        for (int a = 0; a < SEQ; a++)
            for (int b = a+1; b < SEQ; b++)
                for (int c = b+1; c < SEQ; c++) {
                    g_tuples[idx*3+0]=a; g_tuples[idx*3+1]=b; g_tuples[idx*3+2]=c; idx++;
                }
    }
}

// zero svT (pad-K cols must be exactly 0 to not pollute proto)
__global__ void k_zero(){
    size_t i = (size_t)blockIdx.x*256 + threadIdx.x;
    size_t total = (size_t)WAY*HH*DHP*KPAD/8;   // uint4 granules
    if (i < total) ((uint4*)g_svT)[i] = make_uint4(0,0,0,0);
}

__global__ __launch_bounds__(128) void k_prepA(const float* __restrict__ sup,
                                               const float* __restrict__ qry){
    int m = blockIdx.x; int v = m/SEQ, f = m%SEQ;
    const float* src = (v < NS) ? sup + (size_t)m*DIM
                                : qry + ((size_t)(v-NS)*SEQ + f)*DIM;
    for (int i = threadIdx.x; i < DIM; i += 128)
        g_Ap[(size_t)m*DIM + i] = __float2bfloat16(src[i] + g_pe[f*DIM + i]);
}

__global__ void k_transW(const float* __restrict__ kw, const float* __restrict__ vw){
    __shared__ float t[32][33];
    int z = blockIdx.z; int j = z>>1, which = z&1;
    const float* W = which ? vw : kw;
    int o0 = blockIdx.x*32, k0 = blockIdx.y*32;
    int tx = threadIdx.x, ty = threadIdx.y;
    t[ty][tx] = W[(size_t)(j*1152 + k0 + ty)*1152 + o0 + tx];
    __syncthreads();
    g_wT[(size_t)(j*2304 + which*1152 + o0 + ty)*1152 + k0 + tx] = __float2bfloat16(t[tx][ty]);
}

// ---------------- bf16 NT GEMM via mma.sync: C[M,N] = A[M,K] @ B[N,K]^T ----------------
// All of M, N (per grid) padded to 128; K = KT*64. No bounds checks.
__global__ __launch_bounds__(256) void k_gemm(
    const __nv_bfloat16* __restrict__ A, int lda, int amod, size_t sA,
    const __nv_bfloat16* __restrict__ B, int ldb, size_t sB,
    float* __restrict__ C, int ldc, size_t sC, int KT)
{
    extern __shared__ char smem[];
    const int tid = threadIdx.x, wid = tid>>5, lane = tid&31;
    const int wm = wid & 3, wn = wid >> 2;          // 4x2 warp grid
    const int z = blockIdx.z;
    A += (size_t)(amod ? (z % amod) : z) * sA;
    B += (size_t)z * sB;
    C += (size_t)z * sC;
    const int m0 = blockIdx.y*128, n0 = blockIdx.x*128;
    const uint32_t sbase = smem_u32(smem);

    const int lrow = tid >> 3, lch = tid & 7;       // loader: 32 rows per pass
    float acc[2][8][4];
    #pragma unroll
    for (int i=0;i<2;i++) for (int j=0;j<8;j++) for (int r=0;r<4;r++) acc[i][j][r]=0.f;

    // ---- stage loader ----
    auto load_tile = [&](int kt, int buf){
        const __nv_bfloat16* Ab = A + (size_t)m0*lda + kt*64;
        const __nv_bfloat16* Bb = B + (size_t)n0*ldb + kt*64;
        uint32_t da = sbase + buf*32768;
        uint32_t db = da + 16384;
        #pragma unroll
        for (int c = 0; c < 4; c++){
            int row = lrow + c*32;
            uint32_t so = SW128(row*128 + lch*16);
            cpa16(da + so, Ab + (size_t)row*lda + lch*8);
            cpa16(db + so, Bb + (size_t)row*ldb + lch*8);
        }
        asm volatile("cp.async.commit_group;");
    };

    load_tile(0, 0);
    for (int kt = 0; kt < KT; kt++){
        const int buf = kt & 1;
        if (kt + 1 < KT) {
            load_tile(kt+1, buf^1);
            asm volatile("cp.async.wait_group 1;");
        } else {
            asm volatile("cp.async.wait_group 0;");
        }
        __syncthreads();

        const uint32_t sA_ = sbase + buf*32768;
        const uint32_t sB_ = sA_ + 16384;
        #pragma unroll
        for (int kk = 0; kk < 4; kk++){
            const int colb = kk*32 + ((lane >> 4) << 4);
            uint32_t a[2][4], b[4][4];
            #pragma unroll
            for (int i = 0; i < 2; i++){
                int row = wm*32 + i*16 + (lane & 15);
                ldm4(a[i], sA_ + SW128(row*128 + colb));
            }
            #pragma unroll
            for (int j = 0; j < 4; j++){
                int row = wn*64 + j*16 + (lane & 15);
                ldm4(b[j], sB_ + SW128(row*128 + colb));
            }
            #pragma unroll
            for (int i = 0; i < 2; i++)
                #pragma unroll
                for (int jj = 0; jj < 8; jj++)
                    mma16816(acc[i][jj], a[i], b[jj>>1][jj&1], b[jj>>1][2+(jj&1)]);
        }
        __syncthreads();
    }

    // ---- epilogue ----
    #pragma unroll
    for (int i = 0; i < 2; i++){
        int r0 = m0 + wm*32 + i*16 + (lane >> 2);
        #pragma unroll
        for (int jj = 0; jj < 8; jj++){
            int cc = n0 + wn*64 + jj*8 + (lane & 3)*2;
            *(float2*)(C + (size_t)r0*ldc + cc)     = make_float2(acc[i][jj][0], acc[i][jj][1]);
            *(float2*)(C + (size_t)(r0+8)*ldc + cc) = make_float2(acc[i][jj][2], acc[i][jj][3]);
        }
    }
}

// ---------------- tuple combine + bias + LayerNorm ----------------
__global__ __launch_bounds__(128) void k_combine(
    const float* __restrict__ kb, const float* __restrict__ vb,
    const float* __restrict__ lg, const float* __restrict__ lb)
{
    const int bid = blockIdx.x;
    const int v = bid / NTUP, t = bid % NTUP;
    const int tid = threadIdx.x;
    __shared__ float red[128];
    __shared__ int fr[3];
    if (tid < 3) fr[tid] = g_tuples[t*3 + tid];
    __syncthreads();

    float kv[9], vv[9];
    float lsum = 0.f, lsq = 0.f;
    const float* Pb = g_P + (size_t)(v*SEQ)*6912;
    #pragma unroll
    for (int ii = 0; ii < 9; ii++) {
        int d = tid + ii*128;
        float ka = kb[d], va = vb[d];
        #pragma unroll
        for (int j = 0; j < 3; j++) {
            const float* p = g_P + (size_t)(v*SEQ + fr[j])*6912 + j*2304;
            ka += p[d]; va += p[1152 + d];
        }
        kv[ii] = ka; vv[ii] = va;
        lsum += ka; lsq += ka*ka;
    }
    (void)Pb;
    red[tid] = lsum; __syncthreads();
    for (int s = 64; s > 0; s >>= 1) { if (tid < s) red[tid] += red[tid+s]; __syncthreads(); }
    float mu = red[0] * (1.f/1152.f);
    __syncthreads();
    red[tid] = lsq; __syncthreads();
    for (int s = 64; s > 0; s >>= 1) { if (tid < s) red[tid] += red[tid+s]; __syncthreads(); }
    float var = red[0] * (1.f/1152.f) - mu*mu;
    float rstd = rsqrtf(var + 1e-5f);

    int w = 0, s = 0;
    if (v < NS) { w = v / SHOT; s = v % SHOT; }
    #pragma unroll
    for (int ii = 0; ii < 9; ii++) {
        int d = tid + ii*128;
        int h = d / DH, dd = d % DH;
        float o = (kv[ii] - mu) * rstd * lg[d] + lb[d];
        if (v < NS) {
            int zz = w*2 + h;
            g_skz[zz][(size_t)(s*NTUP + t)*DH + dd] = __float2bfloat16(o);
            g_svT[zz][(size_t)dd*KPAD + s*NTUP + t] = __float2bfloat16(vv[ii]);
        } else {
            g_qk[h][(size_t)((v-NS)*NTUP + t)*DH + dd] = __float2bfloat16(o);
            g_qv[(size_t)((v-NS)*NTUP + t)*DIM + d] = vv[ii];
        }
    }
}

// ---------------- softmax: fp32 scores row (1100 of 1152) -> bf16 attn row (1152, zero pad) ----------------
__global__ __launch_bounds__(128) void k_softmax() {
    const int z = blockIdx.x / KROWS;
    const int r = blockIdx.x % KROWS;
    const float* src = g_scores[z] + (size_t)r * SKP;
    __nv_bfloat16* dst = g_attn[z] + (size_t)r * KPAD;
    const int tid = threadIdx.x;
    __shared__ float red[128];
    float ev[9];
    float lmax = -1e30f;
    #pragma unroll
    for (int ii = 0; ii < 9; ii++) {
        int i = tid + ii*128;
        ev[ii] = (i < SKCOL) ? src[i] * (1.f/24.f) : -1e30f;
        lmax = fmaxf(lmax, ev[ii]);
    }
    red[tid] = lmax; __syncthreads();
    for (int s = 64; s > 0; s >>= 1) { if (tid < s) red[tid] = fmaxf(red[tid], red[tid+s]); __syncthreads(); }
    float mx = red[0];
    __syncthreads();
    float lsum = 0.f;
    #pragma unroll
    for (int ii = 0; ii < 9; ii++) {
        int i = tid + ii*128;
        if (i < SKCOL) { ev[ii] = expf(ev[ii] - mx); lsum += ev[ii]; }
        else ev[ii] = 0.f;
    }
    red[tid] = lsum; __syncthreads();
    for (int s = 64; s > 0; s >>= 1) { if (tid < s) red[tid] += red[tid+s]; __syncthreads(); }
    float inv = 1.f / red[0];
    #pragma unroll
    for (int ii = 0; ii < 9; ii++) {
        int i = tid + ii*128;
        dst[i] = __float2bfloat16((i < SKCOL) ? ev[ii] * inv : 0.f);
    }
}

// ---------------- logits ----------------
__global__ __launch_bounds__(256) void k_logits(float* __restrict__ out) {
    const int b = blockIdx.x;       // q*WAY + w
    const int q = b / WAY, w = b % WAY;
    const float* qv = g_qv + (size_t)q * NTUP * DIM;
    float acc = 0.f;
    for (int i = threadIdx.x; i < NTUP*DIM; i += 256) {
        int t = i / DIM, d = i % DIM;
        int h = d / DH, dd = d % DH;
        float p = g_proto[w*2 + h][(size_t)(q*NTUP + t)*DHP + dd];
        float df = qv[i] - p;
        acc += df * df;
    }
    __shared__ float red[256];
    red[threadIdx.x] = acc; __syncthreads();
    for (int s = 128; s > 0; s >>= 1) { if (threadIdx.x < s) red[threadIdx.x] += red[threadIdx.x + s]; __syncthreads(); }
    if (threadIdx.x == 0) out[b] = -red[0] / (float)NTUP;
}

// ---------------- launch ----------------
extern "C" void kernel_launch(void* const* d_in, const int* in_sizes, int n_in,
                              void* d_out, int out_size)
{
    const float* support = (const float*)d_in[0];
    const float* queries = (const float*)d_in[1];
    const float* k_w  = (const float*)d_in[3];
    const float* k_b  = (const float*)d_in[4];
    const float* v_w  = (const float*)d_in[5];
    const float* v_b  = (const float*)d_in[6];
    const float* ln_g = (const float*)d_in[7];
    const float* ln_b = (const float*)d_in[8];
    float* out = (float*)d_out;

    void *pAp, *pWT, *pP, *pQK, *pSKZ, *pSVT, *pSC, *pATT, *pPR;
    cudaGetSymbolAddress(&pAp,  g_Ap);
    cudaGetSymbolAddress(&pWT,  g_wT);
    cudaGetSymbolAddress(&pP,   g_P);
    cudaGetSymbolAddress(&pQK,  g_qk);
    cudaGetSymbolAddress(&pSKZ, g_skz);
    cudaGetSymbolAddress(&pSVT, g_svT);
    cudaGetSymbolAddress(&pSC,  g_scores);
    cudaGetSymbolAddress(&pATT, g_attn);
    cudaGetSymbolAddress(&pPR,  g_proto);

    const int SMEM_BYTES = 65536;
    cudaFuncSetAttribute(k_gemm, cudaFuncAttributeMaxDynamicSharedMemorySize, SMEM_BYTES);

    k_init<<<1, 256>>>();
    {
        size_t tot = (size_t)WAY*HH*DHP*KPAD/8;
        k_zero<<<(int)((tot + 255)/256), 256>>>();
    }
    k_prepA<<<NV*SEQ, 128>>>(support, queries);
    k_transW<<<dim3(36, 36, 6), dim3(32, 32)>>>(k_w, v_w);

    // proj: C[1024(900), 6912] = Ap @ wT^T, K=1152
    k_gemm<<<dim3(54, 8, 1), 256, SMEM_BYTES>>>(
        (const __nv_bfloat16*)pAp, DIM, 1, 0,
        (const __nv_bfloat16*)pWT, DIM, 0,
        (float*)pP, 6912, 0, 18);

    k_combine<<<NV*NTUP, 128>>>(k_b, v_b, ln_g, ln_b);

    // scores: per z: C[11008, 1152] = qk[z%2] @ skz[z]^T, K=576
    k_gemm<<<dim3(SKP/128, MPAD/128, WAY*HH), 256, SMEM_BYTES>>>(
        (const __nv_bfloat16*)pQK, DH, 2, (size_t)MPAD*DH,
        (const __nv_bfloat16*)pSKZ, DH, (size_t)SKP*DH,
        (float*)pSC, SKP, (size_t)MPAD*SKP, 9);

    k_softmax<<<WAY*HH*KROWS, 128>>>();

    // proto: per z: C[11008, 640] = attn[z] @ svT[z]^T, K=1152
    k_gemm<<<dim3(DHP/128, MPAD/128, WAY*HH), 256, SMEM_BYTES>>>(
        (const __nv_bfloat16*)pATT, KPAD, 0, (size_t)MPAD*KPAD,
        (const __nv_bfloat16*)pSVT, KPAD, (size_t)DHP*KPAD,
        (float*)pPR, DHP, (size_t)MPAD*DHP, 18);

    k_logits<<<NQ*WAY, 256>>>(out);
}

// round 4
// speedup vs baseline: 9.5788x; 1.2473x over previous
#include <cuda_runtime.h>
#include <cuda_bf16.h>
#include <math.h>
#include <stdint.h>

#define NS 25
#define NQ 50
#define NV 75
#define SEQ 12
#define DIM 1152
#define HH 2
#define DH 576
#define NTUP 220
#define WAY 5
#define SHOT 5
#define KROWS (NQ*NTUP)      /* 11000 */
#define MPAD  11008          /* 86*128 */
#define SKCOL (SHOT*NTUP)    /* 1100 */
#define SKP   1152
#define DHP   640
#define KPAD  1152

// ---------------- device scratch ----------------
__device__ float g_pe[SEQ*DIM];
__device__ int   g_tuples[NTUP*3];
__device__ __align__(16) __nv_bfloat16 g_Ap[1024*DIM];
__device__ __align__(16) __nv_bfloat16 g_wT[6912*DIM];
__device__ float g_P[1024*6912];
__device__ __align__(16) __nv_bfloat16 g_qk[HH][(size_t)MPAD*DH];
__device__ __align__(16) __nv_bfloat16 g_skz[WAY*HH][(size_t)SKP*DH];
__device__ __align__(16) __nv_bfloat16 g_svT[WAY*HH][(size_t)DHP*KPAD];
__device__ float g_qv[(size_t)KROWS*DIM];
__device__ float g_scores[WAY*HH][(size_t)MPAD*SKP];
__device__ __align__(16) __nv_bfloat16 g_attn[WAY*HH][(size_t)MPAD*KPAD];

// ---------------- helpers ----------------
__device__ __forceinline__ uint32_t smem_u32(const void* p){
    uint32_t a;
    asm("{ .reg .u64 t; cvta.to.shared.u64 t, %1; cvt.u32.u64 %0, t; }" : "=r"(a) : "l"(p));
    return a;
}
#define SW128(x) ((x) ^ (((x)>>3)&0x70))

__device__ __forceinline__ void ldm4(uint32_t* r, uint32_t addr){
    asm volatile("ldmatrix.sync.aligned.m8n8.x4.shared.b16 {%0,%1,%2,%3}, [%4];"
        : "=r"(r[0]), "=r"(r[1]), "=r"(r[2]), "=r"(r[3]) : "r"(addr));
}
__device__ __forceinline__ void mma16816(float* c, const uint32_t* a, uint32_t b0, uint32_t b1){
    asm volatile("mma.sync.aligned.m16n8k16.row.col.f32.bf16.bf16.f32 "
        "{%0,%1,%2,%3}, {%4,%5,%6,%7}, {%8,%9}, {%0,%1,%2,%3};"
        : "+f"(c[0]), "+f"(c[1]), "+f"(c[2]), "+f"(c[3])
        : "r"(a[0]), "r"(a[1]), "r"(a[2]), "r"(a[3]), "r"(b0), "r"(b1));
}
__device__ __forceinline__ void cpa16(uint32_t dst, const void* src){
    asm volatile("cp.async.cg.shared.global [%0], [%1], 16;" :: "r"(dst), "l"(src));
}

// ---------------- init (also zeros the 250-float output) ----------------
__global__ void k_init(float* out) {
    int tid = threadIdx.x;
    for (int i = tid; i < SEQ*576; i += blockDim.x) {
        int p = i / 576, j = i % 576;
        double dv = exp(-(double)(2*j) * (log(10000.0) / 1152.0));
        double ang = (double)p * dv;
        g_pe[p*DIM + 2*j]     = (float)(sin(ang) * 0.1);
        g_pe[p*DIM + 2*j + 1] = (float)(cos(ang) * 0.1);
    }
    if (tid < NQ*WAY) out[tid] = 0.f;
    if (tid == 0) {
        int idx = 0;
        for (int a = 0; a < SEQ; a++)
            for (int b = a+1; b < SEQ; b++)
                for (int c = b+1; c < SEQ; c++) {
                    g_tuples[idx*3+0]=a; g_tuples[idx*3+1]=b; g_tuples[idx*3+2]=c; idx++;
                }
    }
}

__global__ void k_zero(){
    size_t i = (size_t)blockIdx.x*256 + threadIdx.x;
    size_t total = (size_t)WAY*HH*DHP*KPAD/8;
    if (i < total) ((uint4*)g_svT)[i] = make_uint4(0,0,0,0);
}

__global__ __launch_bounds__(128) void k_prepA(const float* __restrict__ sup,
                                               const float* __restrict__ qry){
    int m = blockIdx.x; int v = m/SEQ, f = m%SEQ;
    const float* src = (v < NS) ? sup + (size_t)m*DIM
                                : qry + ((size_t)(v-NS)*SEQ + f)*DIM;
    for (int i = threadIdx.x; i < DIM; i += 128)
        g_Ap[(size_t)m*DIM + i] = __float2bfloat16(src[i] + g_pe[f*DIM + i]);
}

__global__ void k_transW(const float* __restrict__ kw, const float* __restrict__ vw){
    __shared__ float t[32][33];
    int z = blockIdx.z; int j = z>>1, which = z&1;
    const float* W = which ? vw : kw;
    int o0 = blockIdx.x*32, k0 = blockIdx.y*32;
    int tx = threadIdx.x, ty = threadIdx.y;
    t[ty][tx] = W[(size_t)(j*1152 + k0 + ty)*1152 + o0 + tx];
    __syncthreads();
    g_wT[(size_t)(j*2304 + which*1152 + o0 + ty)*1152 + k0 + tx] = __float2bfloat16(t[tx][ty]);
}

// ---------------- bf16 NT GEMM, 3-stage cp.async pipeline ----------------
// C[M,N] = A[M,K] @ B[N,K]^T. M,N multiples of 128, K = KT*64.
// EPI=0: store fp32 C.   EPI=1: fused -(qv - C)^2 reduction -> atomicAdd(out).
template<int EPI>
__global__ __launch_bounds__(256, 2) void k_gemm_t(
    const __nv_bfloat16* __restrict__ A, int lda, int amod, size_t sA,
    const __nv_bfloat16* __restrict__ B, int ldb, size_t sB,
    float* __restrict__ C, int ldc, size_t sC, int KT,
    const float* __restrict__ qv, float* __restrict__ out)
{
    extern __shared__ char smem[];
    const int tid = threadIdx.x, wid = tid>>5, lane = tid&31;
    const int wm = wid & 3, wn = wid >> 2;
    const int z = blockIdx.z;
    A += (size_t)(amod ? (z % amod) : z) * sA;
    B += (size_t)z * sB;
    if (EPI == 0) C += (size_t)z * sC;
    const int m0 = blockIdx.y*128, n0 = blockIdx.x*128;
    const uint32_t sbase = smem_u32(smem);

    const int lrow = tid >> 3, lch = tid & 7;
    float acc[2][8][4];
    #pragma unroll
    for (int i=0;i<2;i++) for (int j=0;j<8;j++) for (int r=0;r<4;r++) acc[i][j][r]=0.f;

    auto load_tile = [&](int kt, int buf){
        const __nv_bfloat16* Ab = A + (size_t)m0*lda + kt*64;
        const __nv_bfloat16* Bb = B + (size_t)n0*ldb + kt*64;
        uint32_t da = sbase + buf*32768;
        uint32_t db = da + 16384;
        #pragma unroll
        for (int c = 0; c < 4; c++){
            int row = lrow + c*32;
            uint32_t so = SW128(row*128 + lch*16);
            cpa16(da + so, Ab + (size_t)row*lda + lch*8);
            cpa16(db + so, Bb + (size_t)row*ldb + lch*8);
        }
        asm volatile("cp.async.commit_group;");
    };

    load_tile(0, 0);
    load_tile(1, 1);

    for (int kt = 0; kt < KT; kt++){
        if (kt + 1 < KT) asm volatile("cp.async.wait_group 1;");
        else             asm volatile("cp.async.wait_group 0;");
        __syncthreads();
        if (kt + 2 < KT) {
            int nb = (kt + 2) % 3;
            load_tile(kt + 2, nb);
        }
        const int buf = kt % 3;
        const uint32_t sA_ = sbase + buf*32768;
        const uint32_t sB_ = sA_ + 16384;
        #pragma unroll
        for (int kk = 0; kk < 4; kk++){
            const int colb = kk*32 + ((lane >> 4) << 4);
            uint32_t a[2][4], b[4][4];
            #pragma unroll
            for (int i = 0; i < 2; i++){
                int row = wm*32 + i*16 + (lane & 15);
                ldm4(a[i], sA_ + SW128(row*128 + colb));
            }
            #pragma unroll
            for (int j = 0; j < 4; j++){
                int row = wn*64 + j*16 + (lane & 15);
                ldm4(b[j], sB_ + SW128(row*128 + colb));
            }
            #pragma unroll
            for (int i = 0; i < 2; i++)
                #pragma unroll
                for (int jj = 0; jj < 8; jj++)
                    mma16816(acc[i][jj], a[i], b[jj>>1][jj&1], b[jj>>1][2+(jj&1)]);
        }
        __syncthreads();
    }

    if (EPI == 0) {
        #pragma unroll
        for (int i = 0; i < 2; i++){
            int r0 = m0 + wm*32 + i*16 + (lane >> 2);
            #pragma unroll
            for (int jj = 0; jj < 8; jj++){
                int cc = n0 + wn*64 + jj*8 + (lane & 3)*2;
                *(float2*)(C + (size_t)r0*ldc + cc)     = make_float2(acc[i][jj][0], acc[i][jj][1]);
                *(float2*)(C + (size_t)(r0+8)*ldc + cc) = make_float2(acc[i][jj][2], acc[i][jj][3]);
            }
        }
    } else {
        // fused logits: proto element P[m][n] pairs with qv[m*DIM + h*DH + n]
        const int w = z >> 1, h = z & 1;
        const int q0 = m0 / NTUP;
        const int qb = (q0 + 1) * NTUP;
        float s[2] = {0.f, 0.f};
        #pragma unroll
        for (int i = 0; i < 2; i++){
            int rb = m0 + wm*32 + i*16 + (lane >> 2);
            #pragma unroll
            for (int rr = 0; rr < 2; rr++){
                int row = rb + rr*8;
                if (row < KROWS) {
                    const float* qrow = qv + (size_t)row*DIM + h*DH;
                    int qi = (row >= qb) ? 1 : 0;
                    float part = 0.f;
                    #pragma unroll
                    for (int jj = 0; jj < 8; jj++){
                        int cc = n0 + wn*64 + jj*8 + (lane & 3)*2;
                        if (cc < DH) {
                            float d0 = qrow[cc]   - acc[i][jj][rr*2+0];
                            float d1 = qrow[cc+1] - acc[i][jj][rr*2+1];
                            part += d0*d0 + d1*d1;
                        }
                    }
                    s[qi] += part;
                }
            }
        }
        float* red = (float*)smem;
        red[tid] = s[0]; red[256 + tid] = s[1];
        __syncthreads();
        #pragma unroll
        for (int st = 128; st > 0; st >>= 1){
            if (tid < st) { red[tid] += red[tid+st]; red[256+tid] += red[256+tid+st]; }
            __syncthreads();
        }
        if (tid == 0 && red[0] != 0.f) atomicAdd(&out[q0*WAY + w], -red[0] * (1.f/NTUP));
        if (tid == 1 && q0 + 1 < NQ && red[256] != 0.f)
            atomicAdd(&out[(q0+1)*WAY + w], -red[256] * (1.f/NTUP));
    }
}

// ---------------- tuple combine + bias + LayerNorm ----------------
__global__ __launch_bounds__(128) void k_combine(
    const float* __restrict__ kb, const float* __restrict__ vb,
    const float* __restrict__ lg, const float* __restrict__ lb)
{
    const int bid = blockIdx.x;
    const int v = bid / NTUP, t = bid % NTUP;
    const int tid = threadIdx.x;
    __shared__ float red[128];
    __shared__ int fr[3];
    if (tid < 3) fr[tid] = g_tuples[t*3 + tid];
    __syncthreads();

    float kv[9], vv[9];
    float lsum = 0.f, lsq = 0.f;
    #pragma unroll
    for (int ii = 0; ii < 9; ii++) {
        int d = tid + ii*128;
        float ka = kb[d], va = vb[d];
        #pragma unroll
        for (int j = 0; j < 3; j++) {
            const float* p = g_P + (size_t)(v*SEQ + fr[j])*6912 + j*2304;
            ka += p[d]; va += p[1152 + d];
        }
        kv[ii] = ka; vv[ii] = va;
        lsum += ka; lsq += ka*ka;
    }
    red[tid] = lsum; __syncthreads();
    for (int s = 64; s > 0; s >>= 1) { if (tid < s) red[tid] += red[tid+s]; __syncthreads(); }
    float mu = red[0] * (1.f/1152.f);
    __syncthreads();
    red[tid] = lsq; __syncthreads();
    for (int s = 64; s > 0; s >>= 1) { if (tid < s) red[tid] += red[tid+s]; __syncthreads(); }
    float var = red[0] * (1.f/1152.f) - mu*mu;
    float rstd = rsqrtf(var + 1e-5f);

    int w = 0, s = 0;
    if (v < NS) { w = v / SHOT; s = v % SHOT; }
    #pragma unroll
    for (int ii = 0; ii < 9; ii++) {
        int d = tid + ii*128;
        int h = d / DH, dd = d % DH;
        float o = (kv[ii] - mu) * rstd * lg[d] + lb[d];
        if (v < NS) {
            int zz = w*2 + h;
            g_skz[zz][(size_t)(s*NTUP + t)*DH + dd] = __float2bfloat16(o);
            g_svT[zz][(size_t)dd*KPAD + s*NTUP + t] = __float2bfloat16(vv[ii]);
        } else {
            g_qk[h][(size_t)((v-NS)*NTUP + t)*DH + dd] = __float2bfloat16(o);
            g_qv[(size_t)((v-NS)*NTUP + t)*DIM + d] = vv[ii];
        }
    }
}

// ---------------- softmax ----------------
__global__ __launch_bounds__(128) void k_softmax() {
    const int z = blockIdx.x / KROWS;
    const int r = blockIdx.x % KROWS;
    const float* src = g_scores[z] + (size_t)r * SKP;
    __nv_bfloat16* dst = g_attn[z] + (size_t)r * KPAD;
    const int tid = threadIdx.x;
    __shared__ float red[128];
    float ev[9];
    float lmax = -1e30f;
    #pragma unroll
    for (int ii = 0; ii < 9; ii++) {
        int i = tid + ii*128;
        ev[ii] = (i < SKCOL) ? src[i] * (1.f/24.f) : -1e30f;
        lmax = fmaxf(lmax, ev[ii]);
    }
    red[tid] = lmax; __syncthreads();
    for (int s = 64; s > 0; s >>= 1) { if (tid < s) red[tid] = fmaxf(red[tid], red[tid+s]); __syncthreads(); }
    float mx = red[0];
    __syncthreads();
    float lsum = 0.f;
    #pragma unroll
    for (int ii = 0; ii < 9; ii++) {
        int i = tid + ii*128;
        if (i < SKCOL) { ev[ii] = expf(ev[ii] - mx); lsum += ev[ii]; }
        else ev[ii] = 0.f;
    }
    red[tid] = lsum; __syncthreads();
    for (int s = 64; s > 0; s >>= 1) { if (tid < s) red[tid] += red[tid+s]; __syncthreads(); }
    float inv = 1.f / red[0];
    #pragma unroll
    for (int ii = 0; ii < 9; ii++) {
        int i = tid + ii*128;
        dst[i] = __float2bfloat16((i < SKCOL) ? ev[ii] * inv : 0.f);
    }
}

// ---------------- launch ----------------
extern "C" void kernel_launch(void* const* d_in, const int* in_sizes, int n_in,
                              void* d_out, int out_size)
{
    const float* support = (const float*)d_in[0];
    const float* queries = (const float*)d_in[1];
    const float* k_w  = (const float*)d_in[3];
    const float* k_b  = (const float*)d_in[4];
    const float* v_w  = (const float*)d_in[5];
    const float* v_b  = (const float*)d_in[6];
    const float* ln_g = (const float*)d_in[7];
    const float* ln_b = (const float*)d_in[8];
    float* out = (float*)d_out;

    void *pAp, *pWT, *pP, *pQK, *pSKZ, *pSVT, *pSC, *pATT, *pQV;
    cudaGetSymbolAddress(&pAp,  g_Ap);
    cudaGetSymbolAddress(&pWT,  g_wT);
    cudaGetSymbolAddress(&pP,   g_P);
    cudaGetSymbolAddress(&pQK,  g_qk);
    cudaGetSymbolAddress(&pSKZ, g_skz);
    cudaGetSymbolAddress(&pSVT, g_svT);
    cudaGetSymbolAddress(&pSC,  g_scores);
    cudaGetSymbolAddress(&pATT, g_attn);
    cudaGetSymbolAddress(&pQV,  g_qv);

    const int SMEM_BYTES = 3*32768;
    cudaFuncSetAttribute(k_gemm_t<0>, cudaFuncAttributeMaxDynamicSharedMemorySize, SMEM_BYTES);
    cudaFuncSetAttribute(k_gemm_t<1>, cudaFuncAttributeMaxDynamicSharedMemorySize, SMEM_BYTES);

    k_init<<<1, 256>>>(out);
    {
        size_t tot = (size_t)WAY*HH*DHP*KPAD/8;
        k_zero<<<(int)((tot + 255)/256), 256>>>();
    }
    k_prepA<<<NV*SEQ, 128>>>(support, queries);
    k_transW<<<dim3(36, 36, 6), dim3(32, 32)>>>(k_w, v_w);

    // proj: C[1024(900), 6912] = Ap @ wT^T, K=1152
    k_gemm_t<0><<<dim3(54, 8, 1), 256, SMEM_BYTES>>>(
        (const __nv_bfloat16*)pAp, DIM, 1, 0,
        (const __nv_bfloat16*)pWT, DIM, 0,
        (float*)pP, 6912, 0, 18, nullptr, nullptr);

    k_combine<<<NV*NTUP, 128>>>(k_b, v_b, ln_g, ln_b);

    // scores: per z: C[11008, 1152] = qk[z%2] @ skz[z]^T, K=576
    k_gemm_t<0><<<dim3(SKP/128, MPAD/128, WAY*HH), 256, SMEM_BYTES>>>(
        (const __nv_bfloat16*)pQK, DH, 2, (size_t)MPAD*DH,
        (const __nv_bfloat16*)pSKZ, DH, (size_t)SKP*DH,
        (float*)pSC, SKP, (size_t)MPAD*SKP, 9, nullptr, nullptr);

    k_softmax<<<WAY*HH*KROWS, 128>>>();

    // proto + fused logits: per z: P = attn[z] @ svT[z]^T, K=1152; reduce (qv-P)^2
    k_gemm_t<1><<<dim3(DHP/128, MPAD/128, WAY*HH), 256, SMEM_BYTES>>>(
        (const __nv_bfloat16*)pATT, KPAD, 0, (size_t)MPAD*KPAD,
        (const __nv_bfloat16*)pSVT, KPAD, (size_t)DHP*KPAD,
        nullptr, 0, 0, 18, (const float*)pQV, out);
}